// round 14
// baseline (speedup 1.0000x reference)
#include <cuda_runtime.h>
#include <cstddef>

// Problem constants
constexpr int B = 8;
constexpr int S = 2048;
constexpr int D = 1024;
constexpr int U = 1024;
constexpr int M = B * S;          // 16384 rows for QKV projection
constexpr float SCORE_SCALE = 0.03125f;   // 1/sqrt(1024)
constexpr float NEG_INF_C = -10000.0f;

// Tiling config
constexpr int BM = 128;
constexpr int BN = 128;
constexpr int BK = 8;
constexpr int NT = 256;

// Device scratch (allocation-free rule: __device__ globals)
__device__ float g_Q[(size_t)M * U];              // 64 MB
__device__ float g_K[(size_t)M * U];              // 64 MB
__device__ float g_V[(size_t)M * U];              // 64 MB
__device__ float g_S[(size_t)B * S * S];          // 128 MB

// ---------------------------------------------------------------------------
// Kernel 1: fused QKV projection.  C = x @ W + b  for W in {Wq, Wk, Wv}
// x: [M, D] row-major;  W: [D, U] row-major.  blockIdx.z selects which.
// ---------------------------------------------------------------------------
__global__ __launch_bounds__(NT) void qkv_kernel(
    const float* __restrict__ x,
    const float* __restrict__ Wq, const float* __restrict__ bq,
    const float* __restrict__ Wk, const float* __restrict__ bk,
    const float* __restrict__ Wv, const float* __restrict__ bv)
{
    __shared__ float As[BK][BM];
    __shared__ float Bs[BK][BN];

    const float* W;
    const float* bias;
    float* out;
    if (blockIdx.z == 0)      { W = Wq; bias = bq; out = g_Q; }
    else if (blockIdx.z == 1) { W = Wk; bias = bk; out = g_K; }
    else                      { W = Wv; bias = bv; out = g_V; }

    const int row0 = blockIdx.y * BM;
    const int col0 = blockIdx.x * BN;
    const int tid  = threadIdx.x;

    const int aRow = tid >> 1;           // 0..127
    const int aCol = (tid & 1) << 2;     // 0 or 4
    const int bRow = tid >> 5;           // 0..7
    const int bCol = (tid & 31) << 2;    // 0..124
    const int ty   = (tid >> 4) << 3;    // row offset in tile
    const int tx   = (tid & 15) << 3;    // col offset in tile

    float acc[8][8] = {};

    for (int k0 = 0; k0 < D; k0 += BK) {
        float4 av = *reinterpret_cast<const float4*>(
            x + (size_t)(row0 + aRow) * D + k0 + aCol);
        As[aCol + 0][aRow] = av.x;
        As[aCol + 1][aRow] = av.y;
        As[aCol + 2][aRow] = av.z;
        As[aCol + 3][aRow] = av.w;
        *reinterpret_cast<float4*>(&Bs[bRow][bCol]) =
            *reinterpret_cast<const float4*>(W + (size_t)(k0 + bRow) * U + col0 + bCol);
        __syncthreads();
#pragma unroll
        for (int kk = 0; kk < BK; ++kk) {
            float a[8], b[8];
            *reinterpret_cast<float4*>(a)     = *reinterpret_cast<const float4*>(&As[kk][ty]);
            *reinterpret_cast<float4*>(a + 4) = *reinterpret_cast<const float4*>(&As[kk][ty + 4]);
            *reinterpret_cast<float4*>(b)     = *reinterpret_cast<const float4*>(&Bs[kk][tx]);
            *reinterpret_cast<float4*>(b + 4) = *reinterpret_cast<const float4*>(&Bs[kk][tx + 4]);
#pragma unroll
            for (int i = 0; i < 8; ++i)
#pragma unroll
                for (int j = 0; j < 8; ++j)
                    acc[i][j] += a[i] * b[j];
        }
        __syncthreads();
    }

    float bb[8];
#pragma unroll
    for (int j = 0; j < 8; ++j) bb[j] = bias[col0 + tx + j];

#pragma unroll
    for (int i = 0; i < 8; ++i) {
        float* orow = out + (size_t)(row0 + ty + i) * U + col0 + tx;
        float4 v0 = make_float4(acc[i][0] + bb[0], acc[i][1] + bb[1],
                                acc[i][2] + bb[2], acc[i][3] + bb[3]);
        float4 v1 = make_float4(acc[i][4] + bb[4], acc[i][5] + bb[5],
                                acc[i][6] + bb[6], acc[i][7] + bb[7]);
        *reinterpret_cast<float4*>(orow)     = v0;
        *reinterpret_cast<float4*>(orow + 4) = v1;
    }
}

// ---------------------------------------------------------------------------
// Kernel 2: scores = (Q @ K^T) * scale + (1 - mq*mk) * NEG_INF   (NT gemm)
// per batch (blockIdx.z).  Q,K: [S, U] row-major.
// ---------------------------------------------------------------------------
__global__ __launch_bounds__(NT) void scores_kernel(const int* __restrict__ mask)
{
    __shared__ float As[BK][BM];
    __shared__ float Bs[BK][BN];

    const int bz = blockIdx.z;
    const float* Q  = g_Q + (size_t)bz * S * U;
    const float* Km = g_K + (size_t)bz * S * U;
    float* out = g_S + (size_t)bz * S * S;

    const int row0 = blockIdx.y * BM;
    const int col0 = blockIdx.x * BN;
    const int tid  = threadIdx.x;

    const int aRow = tid >> 1;
    const int aCol = (tid & 1) << 2;
    const int ty   = (tid >> 4) << 3;
    const int tx   = (tid & 15) << 3;

    float acc[8][8] = {};

    for (int k0 = 0; k0 < U; k0 += BK) {
        float4 av = *reinterpret_cast<const float4*>(
            Q + (size_t)(row0 + aRow) * U + k0 + aCol);
        As[aCol + 0][aRow] = av.x;
        As[aCol + 1][aRow] = av.y;
        As[aCol + 2][aRow] = av.z;
        As[aCol + 3][aRow] = av.w;
        float4 bv = *reinterpret_cast<const float4*>(
            Km + (size_t)(col0 + aRow) * U + k0 + aCol);
        Bs[aCol + 0][aRow] = bv.x;
        Bs[aCol + 1][aRow] = bv.y;
        Bs[aCol + 2][aRow] = bv.z;
        Bs[aCol + 3][aRow] = bv.w;
        __syncthreads();
#pragma unroll
        for (int kk = 0; kk < BK; ++kk) {
            float a[8], b[8];
            *reinterpret_cast<float4*>(a)     = *reinterpret_cast<const float4*>(&As[kk][ty]);
            *reinterpret_cast<float4*>(a + 4) = *reinterpret_cast<const float4*>(&As[kk][ty + 4]);
            *reinterpret_cast<float4*>(b)     = *reinterpret_cast<const float4*>(&Bs[kk][tx]);
            *reinterpret_cast<float4*>(b + 4) = *reinterpret_cast<const float4*>(&Bs[kk][tx + 4]);
#pragma unroll
            for (int i = 0; i < 8; ++i)
#pragma unroll
                for (int j = 0; j < 8; ++j)
                    acc[i][j] += a[i] * b[j];
        }
        __syncthreads();
    }

    const int* mrow = mask + bz * S;
    float mq[8], mk[8];
#pragma unroll
    for (int i = 0; i < 8; ++i) mq[i] = (float)mrow[row0 + ty + i];
#pragma unroll
    for (int j = 0; j < 8; ++j) mk[j] = (float)mrow[col0 + tx + j];

#pragma unroll
    for (int i = 0; i < 8; ++i) {
        float* orow = out + (size_t)(row0 + ty + i) * S + col0 + tx;
#pragma unroll
        for (int j = 0; j < 8; ++j)
            orow[j] = acc[i][j] * SCORE_SCALE + (1.0f - mq[i] * mk[j]) * NEG_INF_C;
    }
}

// ---------------------------------------------------------------------------
// Kernel 3: in-place row softmax over g_S.  One block per row (length 2048).
// ---------------------------------------------------------------------------
__global__ __launch_bounds__(256) void softmax_kernel()
{
    float* p = g_S + (size_t)blockIdx.x * S;
    const int tid = threadIdx.x;

    float4 x0 = reinterpret_cast<const float4*>(p)[tid];
    float4 x1 = reinterpret_cast<const float4*>(p)[tid + 256];
    float v[8] = {x0.x, x0.y, x0.z, x0.w, x1.x, x1.y, x1.z, x1.w};

    float m = v[0];
#pragma unroll
    for (int i = 1; i < 8; ++i) m = fmaxf(m, v[i]);
#pragma unroll
    for (int o = 16; o > 0; o >>= 1) m = fmaxf(m, __shfl_xor_sync(0xFFFFFFFFu, m, o));

    __shared__ float smax[8];
    __shared__ float ssum[8];
    if ((tid & 31) == 0) smax[tid >> 5] = m;
    __syncthreads();
    float mx = smax[0];
#pragma unroll
    for (int i = 1; i < 8; ++i) mx = fmaxf(mx, smax[i]);

    float s = 0.0f;
#pragma unroll
    for (int i = 0; i < 8; ++i) { v[i] = expf(v[i] - mx); s += v[i]; }
#pragma unroll
    for (int o = 16; o > 0; o >>= 1) s += __shfl_xor_sync(0xFFFFFFFFu, s, o);
    if ((tid & 31) == 0) ssum[tid >> 5] = s;
    __syncthreads();
    float tot = 0.0f;
#pragma unroll
    for (int i = 0; i < 8; ++i) tot += ssum[i];
    float inv = 1.0f / tot;

    float4 y0 = make_float4(v[0] * inv, v[1] * inv, v[2] * inv, v[3] * inv);
    float4 y1 = make_float4(v[4] * inv, v[5] * inv, v[6] * inv, v[7] * inv);
    reinterpret_cast<float4*>(p)[tid]       = y0;
    reinterpret_cast<float4*>(p)[tid + 256] = y1;
}

// ---------------------------------------------------------------------------
// Kernel 4: context = P @ V  (NN gemm per batch).  P: [S,S], V: [S,U]
// ---------------------------------------------------------------------------
__global__ __launch_bounds__(NT) void context_kernel(float* __restrict__ out_)
{
    __shared__ float As[BK][BM];
    __shared__ float Bs[BK][BN];

    const int bz = blockIdx.z;
    const float* P = g_S + (size_t)bz * S * S;
    const float* V = g_V + (size_t)bz * S * U;
    float* out = out_ + (size_t)bz * S * U;

    const int row0 = blockIdx.y * BM;
    const int col0 = blockIdx.x * BN;
    const int tid  = threadIdx.x;

    const int aRow = tid >> 1;
    const int aCol = (tid & 1) << 2;
    const int bRow = tid >> 5;
    const int bCol = (tid & 31) << 2;
    const int ty   = (tid >> 4) << 3;
    const int tx   = (tid & 15) << 3;

    float acc[8][8] = {};

    for (int k0 = 0; k0 < S; k0 += BK) {
        float4 av = *reinterpret_cast<const float4*>(
            P + (size_t)(row0 + aRow) * S + k0 + aCol);
        As[aCol + 0][aRow] = av.x;
        As[aCol + 1][aRow] = av.y;
        As[aCol + 2][aRow] = av.z;
        As[aCol + 3][aRow] = av.w;
        *reinterpret_cast<float4*>(&Bs[bRow][bCol]) =
            *reinterpret_cast<const float4*>(V + (size_t)(k0 + bRow) * U + col0 + bCol);
        __syncthreads();
#pragma unroll
        for (int kk = 0; kk < BK; ++kk) {
            float a[8], b[8];
            *reinterpret_cast<float4*>(a)     = *reinterpret_cast<const float4*>(&As[kk][ty]);
            *reinterpret_cast<float4*>(a + 4) = *reinterpret_cast<const float4*>(&As[kk][ty + 4]);
            *reinterpret_cast<float4*>(b)     = *reinterpret_cast<const float4*>(&Bs[kk][tx]);
            *reinterpret_cast<float4*>(b + 4) = *reinterpret_cast<const float4*>(&Bs[kk][tx + 4]);
#pragma unroll
            for (int i = 0; i < 8; ++i)
#pragma unroll
                for (int j = 0; j < 8; ++j)
                    acc[i][j] += a[i] * b[j];
        }
        __syncthreads();
    }

#pragma unroll
    for (int i = 0; i < 8; ++i) {
        float* orow = out + (size_t)(row0 + ty + i) * U + col0 + tx;
        float4 v0 = make_float4(acc[i][0], acc[i][1], acc[i][2], acc[i][3]);
        float4 v1 = make_float4(acc[i][4], acc[i][5], acc[i][6], acc[i][7]);
        *reinterpret_cast<float4*>(orow)     = v0;
        *reinterpret_cast<float4*>(orow + 4) = v1;
    }
}

// ---------------------------------------------------------------------------
extern "C" void kernel_launch(void* const* d_in, const int* in_sizes, int n_in,
                              void* d_out, int out_size)
{
    const float* x    = (const float*)d_in[0];
    const int*   mask = (const int*)  d_in[1];
    const float* Wq   = (const float*)d_in[2];
    const float* bq   = (const float*)d_in[3];
    const float* Wk   = (const float*)d_in[4];
    const float* bk   = (const float*)d_in[5];
    const float* Wv   = (const float*)d_in[6];
    const float* bv   = (const float*)d_in[7];
    float* out = (float*)d_out;

    dim3 blk(NT);
    qkv_kernel<<<dim3(U / BN, M / BM, 3), blk>>>(x, Wq, bq, Wk, bk, Wv, bv);
    scores_kernel<<<dim3(S / BN, S / BM, B), blk>>>(mask);
    softmax_kernel<<<B * S, 256>>>();
    context_kernel<<<dim3(U / BN, S / BM, B), blk>>>(out);
}

// round 15
// speedup vs baseline: 1.0020x; 1.0020x over previous
#include <cuda_runtime.h>
#include <cstddef>

// Problem constants
constexpr int B = 8;
constexpr int S = 2048;
constexpr int D = 1024;
constexpr int U = 1024;
constexpr int M = B * S;          // 16384 rows for QKV projection
constexpr float SCORE_SCALE = 0.03125f;   // 1/sqrt(1024)
constexpr float NEG_INF_C = -10000.0f;

// Tiling config
constexpr int BM = 128;
constexpr int BN = 128;
constexpr int BK = 8;
constexpr int NT = 256;

// Device scratch (allocation-free rule: __device__ globals)
__device__ float g_Q[(size_t)M * U];              // 64 MB
__device__ float g_K[(size_t)M * U];              // 64 MB
__device__ float g_V[(size_t)M * U];              // 64 MB
__device__ float g_S[(size_t)B * S * S];          // 128 MB

// ---------------------------------------------------------------------------
// Kernel 1: fused QKV projection.  C = x @ W + b  for W in {Wq, Wk, Wv}
// x: [M, D] row-major;  W: [D, U] row-major.  blockIdx.z selects which.
// ---------------------------------------------------------------------------
__global__ __launch_bounds__(NT) void qkv_kernel(
    const float* __restrict__ x,
    const float* __restrict__ Wq, const float* __restrict__ bq,
    const float* __restrict__ Wk, const float* __restrict__ bk,
    const float* __restrict__ Wv, const float* __restrict__ bv)
{
    __shared__ float As[BK][BM];
    __shared__ float Bs[BK][BN];

    const float* W;
    const float* bias;
    float* out;
    if (blockIdx.z == 0)      { W = Wq; bias = bq; out = g_Q; }
    else if (blockIdx.z == 1) { W = Wk; bias = bk; out = g_K; }
    else                      { W = Wv; bias = bv; out = g_V; }

    const int row0 = blockIdx.y * BM;
    const int col0 = blockIdx.x * BN;
    const int tid  = threadIdx.x;

    const int aRow = tid >> 1;           // 0..127
    const int aCol = (tid & 1) << 2;     // 0 or 4
    const int bRow = tid >> 5;           // 0..7
    const int bCol = (tid & 31) << 2;    // 0..124
    const int ty   = (tid >> 4) << 3;    // row offset in tile
    const int tx   = (tid & 15) << 3;    // col offset in tile

    float acc[8][8] = {};

    for (int k0 = 0; k0 < D; k0 += BK) {
        float4 av = *reinterpret_cast<const float4*>(
            x + (size_t)(row0 + aRow) * D + k0 + aCol);
        As[aCol + 0][aRow] = av.x;
        As[aCol + 1][aRow] = av.y;
        As[aCol + 2][aRow] = av.z;
        As[aCol + 3][aRow] = av.w;
        *reinterpret_cast<float4*>(&Bs[bRow][bCol]) =
            *reinterpret_cast<const float4*>(W + (size_t)(k0 + bRow) * U + col0 + bCol);
        __syncthreads();
#pragma unroll
        for (int kk = 0; kk < BK; ++kk) {
            float a[8], b[8];
            *reinterpret_cast<float4*>(a)     = *reinterpret_cast<const float4*>(&As[kk][ty]);
            *reinterpret_cast<float4*>(a + 4) = *reinterpret_cast<const float4*>(&As[kk][ty + 4]);
            *reinterpret_cast<float4*>(b)     = *reinterpret_cast<const float4*>(&Bs[kk][tx]);
            *reinterpret_cast<float4*>(b + 4) = *reinterpret_cast<const float4*>(&Bs[kk][tx + 4]);
#pragma unroll
            for (int i = 0; i < 8; ++i)
#pragma unroll
                for (int j = 0; j < 8; ++j)
                    acc[i][j] += a[i] * b[j];
        }
        __syncthreads();
    }

    float bb[8];
#pragma unroll
    for (int j = 0; j < 8; ++j) bb[j] = bias[col0 + tx + j];

#pragma unroll
    for (int i = 0; i < 8; ++i) {
        float* orow = out + (size_t)(row0 + ty + i) * U + col0 + tx;
        float4 v0 = make_float4(acc[i][0] + bb[0], acc[i][1] + bb[1],
                                acc[i][2] + bb[2], acc[i][3] + bb[3]);
        float4 v1 = make_float4(acc[i][4] + bb[4], acc[i][5] + bb[5],
                                acc[i][6] + bb[6], acc[i][7] + bb[7]);
        *reinterpret_cast<float4*>(orow)     = v0;
        *reinterpret_cast<float4*>(orow + 4) = v1;
    }
}

// ---------------------------------------------------------------------------
// Kernel 2: scores = (Q @ K^T) * scale + (1 - mq*mk) * NEG_INF   (NT gemm)
// per batch (blockIdx.z).  Q,K: [S, U] row-major.
// ---------------------------------------------------------------------------
__global__ __launch_bounds__(NT) void scores_kernel(const int* __restrict__ mask)
{
    __shared__ float As[BK][BM];
    __shared__ float Bs[BK][BN];

    const int bz = blockIdx.z;
    const float* Q  = g_Q + (size_t)bz * S * U;
    const float* Km = g_K + (size_t)bz * S * U;
    float* out = g_S + (size_t)bz * S * S;

    const int row0 = blockIdx.y * BM;
    const int col0 = blockIdx.x * BN;
    const int tid  = threadIdx.x;

    const int aRow = tid >> 1;
    const int aCol = (tid & 1) << 2;
    const int ty   = (tid >> 4) << 3;
    const int tx   = (tid & 15) << 3;

    float acc[8][8] = {};

    for (int k0 = 0; k0 < U; k0 += BK) {
        float4 av = *reinterpret_cast<const float4*>(
            Q + (size_t)(row0 + aRow) * U + k0 + aCol);
        As[aCol + 0][aRow] = av.x;
        As[aCol + 1][aRow] = av.y;
        As[aCol + 2][aRow] = av.z;
        As[aCol + 3][aRow] = av.w;
        float4 bv = *reinterpret_cast<const float4*>(
            Km + (size_t)(col0 + aRow) * U + k0 + aCol);
        Bs[aCol + 0][aRow] = bv.x;
        Bs[aCol + 1][aRow] = bv.y;
        Bs[aCol + 2][aRow] = bv.z;
        Bs[aCol + 3][aRow] = bv.w;
        __syncthreads();
#pragma unroll
        for (int kk = 0; kk < BK; ++kk) {
            float a[8], b[8];
            *reinterpret_cast<float4*>(a)     = *reinterpret_cast<const float4*>(&As[kk][ty]);
            *reinterpret_cast<float4*>(a + 4) = *reinterpret_cast<const float4*>(&As[kk][ty + 4]);
            *reinterpret_cast<float4*>(b)     = *reinterpret_cast<const float4*>(&Bs[kk][tx]);
            *reinterpret_cast<float4*>(b + 4) = *reinterpret_cast<const float4*>(&Bs[kk][tx + 4]);
#pragma unroll
            for (int i = 0; i < 8; ++i)
#pragma unroll
                for (int j = 0; j < 8; ++j)
                    acc[i][j] += a[i] * b[j];
        }
        __syncthreads();
    }

    const int* mrow = mask + bz * S;
    float mq[8], mk[8];
#pragma unroll
    for (int i = 0; i < 8; ++i) mq[i] = (float)mrow[row0 + ty + i];
#pragma unroll
    for (int j = 0; j < 8; ++j) mk[j] = (float)mrow[col0 + tx + j];

#pragma unroll
    for (int i = 0; i < 8; ++i) {
        float* orow = out + (size_t)(row0 + ty + i) * S + col0 + tx;
#pragma unroll
        for (int j = 0; j < 8; ++j)
            orow[j] = acc[i][j] * SCORE_SCALE + (1.0f - mq[i] * mk[j]) * NEG_INF_C;
    }
}

// ---------------------------------------------------------------------------
// Kernel 3: in-place row softmax over g_S.  One block per row (length 2048).
// ---------------------------------------------------------------------------
__global__ __launch_bounds__(256) void softmax_kernel()
{
    float* p = g_S + (size_t)blockIdx.x * S;
    const int tid = threadIdx.x;

    float4 x0 = reinterpret_cast<const float4*>(p)[tid];
    float4 x1 = reinterpret_cast<const float4*>(p)[tid + 256];
    float v[8] = {x0.x, x0.y, x0.z, x0.w, x1.x, x1.y, x1.z, x1.w};

    float m = v[0];
#pragma unroll
    for (int i = 1; i < 8; ++i) m = fmaxf(m, v[i]);
#pragma unroll
    for (int o = 16; o > 0; o >>= 1) m = fmaxf(m, __shfl_xor_sync(0xFFFFFFFFu, m, o));

    __shared__ float smax[8];
    __shared__ float ssum[8];
    if ((tid & 31) == 0) smax[tid >> 5] = m;
    __syncthreads();
    float mx = smax[0];
#pragma unroll
    for (int i = 1; i < 8; ++i) mx = fmaxf(mx, smax[i]);

    float s = 0.0f;
#pragma unroll
    for (int i = 0; i < 8; ++i) { v[i] = expf(v[i] - mx); s += v[i]; }
#pragma unroll
    for (int o = 16; o > 0; o >>= 1) s += __shfl_xor_sync(0xFFFFFFFFu, s, o);
    if ((tid & 31) == 0) ssum[tid >> 5] = s;
    __syncthreads();
    float tot = 0.0f;
#pragma unroll
    for (int i = 0; i < 8; ++i) tot += ssum[i];
    float inv = 1.0f / tot;

    float4 y0 = make_float4(v[0] * inv, v[1] * inv, v[2] * inv, v[3] * inv);
    float4 y1 = make_float4(v[4] * inv, v[5] * inv, v[6] * inv, v[7] * inv);
    reinterpret_cast<float4*>(p)[tid]       = y0;
    reinterpret_cast<float4*>(p)[tid + 256] = y1;
}

// ---------------------------------------------------------------------------
// Kernel 4: context = P @ V  (NN gemm per batch).  P: [S,S], V: [S,U]
// ---------------------------------------------------------------------------
__global__ __launch_bounds__(NT) void context_kernel(float* __restrict__ out_)
{
    __shared__ float As[BK][BM];
    __shared__ float Bs[BK][BN];

    const int bz = blockIdx.z;
    const float* P = g_S + (size_t)bz * S * S;
    const float* V = g_V + (size_t)bz * S * U;
    float* out = out_ + (size_t)bz * S * U;

    const int row0 = blockIdx.y * BM;
    const int col0 = blockIdx.x * BN;
    const int tid  = threadIdx.x;

    const int aRow = tid >> 1;
    const int aCol = (tid & 1) << 2;
    const int bRow = tid >> 5;
    const int bCol = (tid & 31) << 2;
    const int ty   = (tid >> 4) << 3;
    const int tx   = (tid & 15) << 3;

    float acc[8][8] = {};

    for (int k0 = 0; k0 < S; k0 += BK) {
        float4 av = *reinterpret_cast<const float4*>(
            P + (size_t)(row0 + aRow) * S + k0 + aCol);
        As[aCol + 0][aRow] = av.x;
        As[aCol + 1][aRow] = av.y;
        As[aCol + 2][aRow] = av.z;
        As[aCol + 3][aRow] = av.w;
        *reinterpret_cast<float4*>(&Bs[bRow][bCol]) =
            *reinterpret_cast<const float4*>(V + (size_t)(k0 + bRow) * U + col0 + bCol);
        __syncthreads();
#pragma unroll
        for (int kk = 0; kk < BK; ++kk) {
            float a[8], b[8];
            *reinterpret_cast<float4*>(a)     = *reinterpret_cast<const float4*>(&As[kk][ty]);
            *reinterpret_cast<float4*>(a + 4) = *reinterpret_cast<const float4*>(&As[kk][ty + 4]);
            *reinterpret_cast<float4*>(b)     = *reinterpret_cast<const float4*>(&Bs[kk][tx]);
            *reinterpret_cast<float4*>(b + 4) = *reinterpret_cast<const float4*>(&Bs[kk][tx + 4]);
#pragma unroll
            for (int i = 0; i < 8; ++i)
#pragma unroll
                for (int j = 0; j < 8; ++j)
                    acc[i][j] += a[i] * b[j];
        }
        __syncthreads();
    }

#pragma unroll
    for (int i = 0; i < 8; ++i) {
        float* orow = out + (size_t)(row0 + ty + i) * U + col0 + tx;
        float4 v0 = make_float4(acc[i][0], acc[i][1], acc[i][2], acc[i][3]);
        float4 v1 = make_float4(acc[i][4], acc[i][5], acc[i][6], acc[i][7]);
        *reinterpret_cast<float4*>(orow)     = v0;
        *reinterpret_cast<float4*>(orow + 4) = v1;
    }
}

// ---------------------------------------------------------------------------
extern "C" void kernel_launch(void* const* d_in, const int* in_sizes, int n_in,
                              void* d_out, int out_size)
{
    const float* x    = (const float*)d_in[0];
    const int*   mask = (const int*)  d_in[1];
    const float* Wq   = (const float*)d_in[2];
    const float* bq   = (const float*)d_in[3];
    const float* Wk   = (const float*)d_in[4];
    const float* bk   = (const float*)d_in[5];
    const float* Wv   = (const float*)d_in[6];
    const float* bv   = (const float*)d_in[7];
    float* out = (float*)d_out;

    dim3 blk(NT);
    qkv_kernel<<<dim3(U / BN, M / BM, 3), blk>>>(x, Wq, bq, Wk, bk, Wv, bv);
    scores_kernel<<<dim3(S / BN, S / BM, B), blk>>>(mask);
    softmax_kernel<<<B * S, 256>>>();
    context_kernel<<<dim3(U / BN, S / BM, B), blk>>>(out);
}